// round 10
// baseline (speedup 1.0000x reference)
#include <cuda_runtime.h>
#include <cuda_fp16.h>
#include <math.h>

#define N_ATOMS 768
#define NM1 767
#define NEDGE (768*767)
#define DIM 64
#define NC 50
#define TABM 768
#define TABRO 512
#define CUTF 5.0f
#define GAPF (5.0f/49.0f)
#define INVH ((float)(TABM-1)/CUTF)
#define INVHRO ((float)(TABRO-1)/CUTF)
#define LN2F 0.69314718055994531f

#define NSPLIT 24
#define IPB (N_ATOMS/NSPLIT)     // 32 i-rows per block
#define JPB 16                   // 16 dst per block

#define SMEM_UPD ((3*4096 + 3*256 + 64)*4)   // 52480 B

// ---- scratch (static device allocations; no runtime alloc) ----
__device__ float g_h[N_ATOMS*DIM];
__device__ float g_nw[N_ATOMS*DIM];
__device__ float g_aggp[NSPLIT][N_ATOMS*DIM];  // per-i-split partial aggregates
__device__ float g_ha[N_ATOMS];
// paired-row tables: entry t = {row t, row t+1}; per lane g: 16B at t*256 + g*16
// layer tables fp16: TABM*128 halves = 192KB per layer
__device__ __align__(256) __half g_tab2[3][TABM*128];
// readout table fp16 paired: TABRO*128 halves = 128KB
__device__ __align__(256) __half g_tabro2[TABRO*128];

__device__ __forceinline__ float sp05(float x){   // Softplus(beta=0.5, thr=14)
    float bx = 0.5f*x;
    return bx > 14.0f ? x : 2.0f*log1pf(expf(bx));
}
__device__ __forceinline__ float sp1(float x){    // Softplus(beta=1, thr=20)
    return x > 20.0f ? x : log1pf(expf(x));
}

// pair-layout half offset for row value of dim c: lo slot in pair[t], hi slot in pair[t-1]
__device__ __forceinline__ int pair_lo(int t, int c){ return t*128 + ((c>>2)<<3) + (c&3); }
__device__ __forceinline__ int pair_hi(int t, int c){ return t*128 + ((c>>2)<<3) + 4 + (c&3); }

// ---- fused preamble: paired tables + h/nw init ----
// blocks [0,768): layer tabs ; [768,1280): ro ; [1280,2048): init
__global__ void k_pre(const float* __restrict__ pw1, const float* __restrict__ pb1,
                      const float* __restrict__ pw2, const float* __restrict__ pb2,
                      const float* __restrict__ row1, const float* __restrict__ rob1,
                      const int* __restrict__ at, const float* __restrict__ emb,
                      const float* __restrict__ w1){
    int b = blockIdx.x, c = threadIdx.x;
    __shared__ float sbuf[DIM];
    __shared__ float rbf[NC];
    if (b < TABM){
        float d = (float)b * (CUTF/(float)(TABM-1));
        if (c < NC){ float t = d - (float)c*GAPF; rbf[c] = expf(-t*t*(1.0f/GAPF)); }
        __syncthreads();
        for (int l=0;l<3;l++){
            float u0 = pb1[l*DIM+c], u1 = 0.f;
            #pragma unroll 10
            for (int k=0;k<NC-1;k+=2){
                u0 = fmaf(rbf[k],   pw1[(l*NC+k)*DIM+c],   u0);
                u1 = fmaf(rbf[k+1], pw1[(l*NC+k+1)*DIM+c], u1);
            }
            u0 = fmaf(rbf[NC-1], pw1[(l*NC+NC-1)*DIM+c], u0);
            float s = sp05(u0 + u1);
            sbuf[c] = s; __syncthreads();
            float e0 = pb2[l*DIM+c], e1 = 0.f;
            #pragma unroll 8
            for (int k=0;k<DIM;k+=2){
                e0 = fmaf(sbuf[k],   pw2[(l*DIM+k)*DIM+c],   e0);
                e1 = fmaf(sbuf[k+1], pw2[(l*DIM+k+1)*DIM+c], e1);
            }
            __half hv = __float2half(e0 + e1);
            if (b <= TABM-2) g_tab2[l][pair_lo(b, c)]   = hv;   // row b = lo of pair b
            if (b >= 1)      g_tab2[l][pair_hi(b-1, c)] = hv;   // row b = hi of pair b-1
            __syncthreads();
        }
    } else if (b < TABM + TABRO){
        int m = b - TABM;
        float d = (float)m * (CUTF/(float)(TABRO-1));
        if (c < NC){ float t = d - (float)c*GAPF; rbf[c] = expf(-t*t*(1.0f/GAPF)); }
        __syncthreads();
        float v0 = rob1[c], v1 = 0.f;
        #pragma unroll 10
        for (int k=0;k<NC-1;k+=2){
            v0 = fmaf(rbf[k],   row1[(2+k)*DIM+c],   v0);
            v1 = fmaf(rbf[k+1], row1[(2+k+1)*DIM+c], v1);
        }
        v0 = fmaf(rbf[NC-1], row1[(2+NC-1)*DIM+c], v0);
        __half hv = __float2half(v0 + v1);
        if (m <= TABRO-2) g_tabro2[pair_lo(m, c)]   = hv;
        if (m >= 1)       g_tabro2[pair_hi(m-1, c)] = hv;
    } else {
        int n = b - TABM - TABRO;
        float hv = emb[at[n]*DIM + c];
        sbuf[c] = hv; g_h[n*DIM+c] = hv;
        __syncthreads();
        float a0 = 0.f, a1 = 0.f;
        #pragma unroll 8
        for (int k=0;k<DIM;k+=2){
            a0 = fmaf(sbuf[k],   w1[k*DIM+c],     a0);
            a1 = fmaf(sbuf[k+1], w1[(k+1)*DIM+c], a1);
        }
        g_nw[n*DIM+c] = a0 + a1;
    }
}

// ---- message pass: aggp[isp][j] = sum_{i in split, i != j} nw[i] * lerp(tab_l, d_ij)
// grid (48, 24). One LDG.128 per lane-edge from paired table; HFMA2 lerp;
// branchless with analytic i==j correction (f=0 lerp is exact in half).
__global__ void __launch_bounds__(256,6) k_msg(const float* __restrict__ dist, int l){
    __shared__ float4 nw_s[IPB*16];     // 8 KB
    __shared__ uint2  ed_s[IPB*JPB];    // 4 KB : {f packed half2, t*256}

    int tid  = threadIdx.x;
    int grp  = tid >> 4;         // j within tile
    int g    = tid & 15;         // float4 lane
    int jbase = blockIdx.x * JPB;
    int ibase = blockIdx.y * IPB;
    int j     = jbase + grp;

    // stage nw chunk (IPB*16 float4 = 512), coalesced register-batched
    {
        const float4* __restrict__ nwg = (const float4*)g_nw + ibase*16;
        float4 rn[2];
        #pragma unroll
        for (int q=0;q<2;q++) rn[q] = __ldg(nwg + tid + 256*q);
        #pragma unroll
        for (int q=0;q<2;q++) nw_s[tid + 256*q] = rn[q];
    }
    // stage per-edge (f half2, byte offset t*256): index math ONCE per edge
    {
        uint2 rd[2];
        #pragma unroll
        for (int q=0;q<2;q++){
            int s = tid + 256*q;
            int il = s >> 4, jj = s & 15;
            int i = ibase + il, jd = jbase + jj;
            float dv = (i != jd) ? __ldg(dist + i*NM1 + jd - (jd > i)) : 0.f;
            float x = dv * INVH;
            int t = min((int)x, TABM-2);
            __half2 f2 = __float2half2_rn(x - (float)t);
            rd[q] = make_uint2(*reinterpret_cast<unsigned*>(&f2), (unsigned)t * 256u);
        }
        #pragma unroll
        for (int q=0;q<2;q++) ed_s[tid + 256*q] = rd[q];
    }
    __syncthreads();

    const char* __restrict__ tp = (const char*)g_tab2[l] + g*16;
    float4 acc = make_float4(0.f,0.f,0.f,0.f);
    #pragma unroll 4
    for (int il = 0; il < IPB; il++){
        uint2 ed = ed_s[il*16 + grp];
        uint4 a = __ldg((const uint4*)(tp + ed.y));   // {lo01, lo23, hi01, hi23}
        __half2 f2  = *reinterpret_cast<__half2*>(&ed.x);
        __half2 lo0 = *reinterpret_cast<__half2*>(&a.x);
        __half2 lo1 = *reinterpret_cast<__half2*>(&a.y);
        __half2 hi0 = *reinterpret_cast<__half2*>(&a.z);
        __half2 hi1 = *reinterpret_cast<__half2*>(&a.w);
        __half2 r0 = __hfma2(f2, __hsub2(hi0, lo0), lo0);
        __half2 r1 = __hfma2(f2, __hsub2(hi1, lo1), lo1);
        float4 w = nw_s[il*16 + g];
        acc.x = fmaf(w.x, __low2float(r0),  acc.x);
        acc.y = fmaf(w.y, __high2float(r0), acc.y);
        acc.z = fmaf(w.z, __low2float(r1),  acc.z);
        acc.w = fmaf(w.w, __high2float(r1), acc.w);
    }
    // remove i==j self-term (computed with d=0 -> exact pair[0].lo)
    int jl = j - ibase;
    if (jl >= 0 && jl < IPB){
        uint4 a = *(const uint4*)tp;    // pair 0
        float2 u0 = __half22float2(*reinterpret_cast<const __half2*>(&a.x));
        float2 u1 = __half22float2(*reinterpret_cast<const __half2*>(&a.y));
        float4 w  = nw_s[jl*16 + g];
        acc.x -= w.x*u0.x; acc.y -= w.y*u0.y;
        acc.z -= w.z*u1.x; acc.w -= w.w*u1.y;
    }
    ((float4*)g_aggp[blockIdx.y])[j*16 + g] = acc;
}

// ---- node update: h += MLP(sum of agg partials); then nw for next layer, or ha ----
__global__ void __launch_bounds__(256) k_upd(int l, int last,
        const float* __restrict__ qw1, const float* __restrict__ qb1,
        const float* __restrict__ qw2, const float* __restrict__ qb2,
        const float* __restrict__ w1,
        const float* __restrict__ auw1, const float* __restrict__ aub1,
        const float* __restrict__ auw2, const float* __restrict__ aub2){
    extern __shared__ float sm[];
    float* wA  = sm;            // qw1[l]
    float* wB  = sm + 4096;     // qw2[l]
    float* wC  = sm + 8192;     // w1[l+1] or au_w1
    float* sa  = sm + 12288;
    float* st  = sm + 12544;
    float* sh  = sm + 12800;
    float* au2 = sm + 13056;

    int tid = threadIdx.x;
    int nd  = tid >> 6;
    int c   = tid & 63;
    int n   = blockIdx.x*4 + nd;

    {
        const float4* A4 = (const float4*)(qw1 + l*DIM*DIM);
        const float4* B4 = (const float4*)(qw2 + l*DIM*DIM);
        const float4* C4 = (const float4*)(last ? auw1 : (w1 + (l+1)*DIM*DIM));
        float4 ra[4], rb[4], rc[4];
        #pragma unroll
        for (int q=0;q<4;q++){
            ra[q] = __ldg(A4 + tid + 256*q);
            rb[q] = __ldg(B4 + tid + 256*q);
            rc[q] = __ldg(C4 + tid + 256*q);
        }
        #pragma unroll
        for (int q=0;q<4;q++){
            ((float4*)wA)[tid + 256*q] = ra[q];
            ((float4*)wB)[tid + 256*q] = rb[q];
            ((float4*)wC)[tid + 256*q] = rc[q];
        }
    }
    if (last && tid < DIM) au2[tid] = auw2[tid];

    int off = n*DIM + c;
    float a = 0.f;
    #pragma unroll
    for (int s = 0; s < NSPLIT; s++) a += g_aggp[s][off];
    sa[nd*DIM + c] = a;
    __syncthreads();

    float u0 = qb1[l*DIM+c], u1 = 0.f, u2 = 0.f, u3 = 0.f;
    #pragma unroll 4
    for (int k=0;k<DIM;k+=4){
        u0 = fmaf(sa[nd*DIM+k],   wA[k*DIM+c],     u0);
        u1 = fmaf(sa[nd*DIM+k+1], wA[(k+1)*DIM+c], u1);
        u2 = fmaf(sa[nd*DIM+k+2], wA[(k+2)*DIM+c], u2);
        u3 = fmaf(sa[nd*DIM+k+3], wA[(k+3)*DIM+c], u3);
    }
    st[nd*DIM + c] = sp05((u0+u1)+(u2+u3));
    __syncthreads();

    float p0 = qb2[l*DIM+c], p1 = 0.f, p2 = 0.f, p3 = 0.f;
    #pragma unroll 4
    for (int k=0;k<DIM;k+=4){
        p0 = fmaf(st[nd*DIM+k],   wB[k*DIM+c],     p0);
        p1 = fmaf(st[nd*DIM+k+1], wB[(k+1)*DIM+c], p1);
        p2 = fmaf(st[nd*DIM+k+2], wB[(k+2)*DIM+c], p2);
        p3 = fmaf(st[nd*DIM+k+3], wB[(k+3)*DIM+c], p3);
    }
    float hn = g_h[off] + ((p0+p1)+(p2+p3));
    g_h[off] = hn;
    sh[nd*DIM + c] = hn;
    __syncthreads();

    if (!last){
        float a0 = 0.f, a1 = 0.f, a2 = 0.f, a3 = 0.f;
        #pragma unroll 4
        for (int k=0;k<DIM;k+=4){
            a0 = fmaf(sh[nd*DIM+k],   wC[k*DIM+c],     a0);
            a1 = fmaf(sh[nd*DIM+k+1], wC[(k+1)*DIM+c], a1);
            a2 = fmaf(sh[nd*DIM+k+2], wC[(k+2)*DIM+c], a2);
            a3 = fmaf(sh[nd*DIM+k+3], wC[(k+3)*DIM+c], a3);
        }
        g_nw[off] = (a0+a1)+(a2+a3);
    } else {
        float a0 = aub1[c], a1 = 0.f, a2 = 0.f, a3 = 0.f;
        #pragma unroll 4
        for (int k=0;k<DIM;k+=4){
            a0 = fmaf(sh[nd*DIM+k],   wC[k*DIM+c],     a0);
            a1 = fmaf(sh[nd*DIM+k+1], wC[(k+1)*DIM+c], a1);
            a2 = fmaf(sh[nd*DIM+k+2], wC[(k+2)*DIM+c], a2);
            a3 = fmaf(sh[nd*DIM+k+3], wC[(k+3)*DIM+c], a3);
        }
        st[nd*DIM + c] = sp1((a0+a1)+(a2+a3)) - LN2F;
        __syncthreads();
        if (c == 0){
            float acc2 = aub2[0];
            #pragma unroll 8
            for (int k=0;k<DIM;k++) acc2 = fmaf(st[nd*DIM+k], au2[k], acc2);
            g_ha[n] = acc2;
        }
    }
}

// ---- readout: i-major; per-edge scalars staged in smem; paired fp16 table ----
__global__ void __launch_bounds__(256) k_readout(const float* __restrict__ dist,
        const float* __restrict__ row1, const float* __restrict__ row2,
        const float* __restrict__ rob2, float* __restrict__ out){
    __shared__ float4 ed_s[NM1 + 1];
    int i   = blockIdx.x;
    int tid = threadIdx.x;
    int grp = tid >> 4;
    int g   = tid & 15;
    long ebase = (long)i * NM1;

    // stage per-edge scalars: f, byte-offset into paired ro table, hj
    for (int r = tid; r < NM1; r += 256){
        int jd = r + (r >= i);
        float d = __ldg(dist + ebase + r);
        float x = d * INVHRO;
        int t = min((int)x, TABRO-2);
        float hj = __ldg(g_ha + jd);
        ed_s[r] = make_float4(x - (float)t, __uint_as_float((unsigned)t * 256u), hj, 0.f);
    }

    float4 wa  = __ldg((const float4*)row1 + g);          // ro_w1 row 0 (ha_src)
    float4 wb  = __ldg((const float4*)(row1 + DIM) + g);  // ro_w1 row 1 (ha_dst)
    float4 w2a = __ldg((const float4*)row2 + 2*g);
    float4 w2b = __ldg((const float4*)row2 + 2*g + 1);
    float b20 = rob2[0], b21 = rob2[1];
    float hi = __ldg(g_ha + i);
    float4 base = make_float4(hi*wa.x, hi*wa.y, hi*wa.z, hi*wa.w);
    const char* tp = (const char*)g_tabro2 + g*16;
    __syncthreads();

    for (int r = grp; r < NM1; r += 16){
        float4 ed = ed_s[r];
        uint4 a = __ldg((const uint4*)(tp + __float_as_uint(ed.y)));
        float2 u0 = __half22float2(*reinterpret_cast<const __half2*>(&a.x));
        float2 u1 = __half22float2(*reinterpret_cast<const __half2*>(&a.y));
        float2 v0 = __half22float2(*reinterpret_cast<const __half2*>(&a.z));
        float2 v1 = __half22float2(*reinterpret_cast<const __half2*>(&a.w));
        float f = ed.x, hj = ed.z;
        float z0 = fmaxf(fmaf(hj, wb.x, fmaf(f, v0.x-u0.x, u0.x) + base.x), 0.f);
        float z1 = fmaxf(fmaf(hj, wb.y, fmaf(f, v0.y-u0.y, u0.y) + base.y), 0.f);
        float z2 = fmaxf(fmaf(hj, wb.z, fmaf(f, v1.x-u1.x, u1.x) + base.z), 0.f);
        float z3 = fmaxf(fmaf(hj, wb.w, fmaf(f, v1.y-u1.y, u1.y) + base.w), 0.f);
        float a0 = z0*w2a.x + z1*w2a.z + z2*w2b.x + z3*w2b.z;
        float a1 = z0*w2a.y + z1*w2a.w + z2*w2b.y + z3*w2b.w;
        #pragma unroll
        for (int off=8; off; off>>=1){
            a0 += __shfl_xor_sync(0xffffffffu, a0, off);
            a1 += __shfl_xor_sync(0xffffffffu, a1, off);
        }
        if (g == 0){
            float l0 = a0 + b20, l1 = a1 + b21;
            float m = fmaxf(l0, l1);
            float e0 = __expf(l0 - m), e1 = __expf(l1 - m);
            float inv = 1.0f/(e0 + e1);
            ((float2*)out)[ebase + r] = make_float2(e0*inv, e1*inv);
        }
    }
}

extern "C" void kernel_launch(void* const* d_in, const int* in_sizes, int n_in,
                              void* d_out, int out_size){
    const int*   at   = (const int*)  d_in[0];
    const float* dist = (const float*)d_in[1];
    // d_in[2]=src, d_in[3]=dst (recomputed analytically; complete graph)
    const float* emb  = (const float*)d_in[4];
    const float* w1   = (const float*)d_in[5];
    const float* pw1  = (const float*)d_in[6];
    const float* pb1  = (const float*)d_in[7];
    const float* pw2  = (const float*)d_in[8];
    const float* pb2  = (const float*)d_in[9];
    const float* qw1  = (const float*)d_in[10];
    const float* qb1  = (const float*)d_in[11];
    const float* qw2  = (const float*)d_in[12];
    const float* qb2  = (const float*)d_in[13];
    const float* auw1 = (const float*)d_in[14];
    const float* aub1 = (const float*)d_in[15];
    const float* auw2 = (const float*)d_in[16];
    const float* aub2 = (const float*)d_in[17];
    const float* row1 = (const float*)d_in[18];
    const float* rob1 = (const float*)d_in[19];
    const float* row2 = (const float*)d_in[20];
    const float* rob2 = (const float*)d_in[21];
    float* out = (float*)d_out;

    cudaFuncSetAttribute(k_upd, cudaFuncAttributeMaxDynamicSharedMemorySize, SMEM_UPD);

    // launch index for ncu -s 5: 0:pre 1:msg 2:upd 3:msg 4:upd 5:msg <- profiled
    k_pre<<<TABM + TABRO + N_ATOMS, 64>>>(pw1, pb1, pw2, pb2, row1, rob1, at, emb, w1);
    for (int l = 0; l < 3; l++){
        k_msg<<<dim3(48, NSPLIT), 256>>>(dist, l);
        k_upd<<<192, 256, SMEM_UPD>>>(l, (l==2) ? 1 : 0, qw1, qb1, qw2, qb2, w1,
                                      auw1, aub1, auw2, aub2);
    }
    k_readout<<<N_ATOMS, 256>>>(dist, row1, row2, rob2, out);
}

// round 13
// speedup vs baseline: 1.0666x; 1.0666x over previous
#include <cuda_runtime.h>
#include <cuda_fp16.h>
#include <math.h>

#define N_ATOMS 768
#define NM1 767
#define NEDGE (768*767)
#define DIM 64
#define NC 50
#define TABM 384                 // paired fp16 layer table rows -> 96KB/layer (L1-resident)
#define TABRO 512
#define CUTF 5.0f
#define GAPF (5.0f/49.0f)
#define INVH ((float)(TABM-1)/CUTF)
#define INVHRO ((float)(TABRO-1)/CUTF)
#define LN2F 0.69314718055994531f

#define NSPLIT 24
#define IPB (N_ATOMS/NSPLIT)     // 32 i-rows per block
#define JPB 16                   // 16 dst per block

#define SMEM_UPD ((3*4096 + 3*256 + 64)*4)   // 52480 B

// ---- scratch (static device allocations; no runtime alloc) ----
__device__ float g_h[N_ATOMS*DIM];
__device__ float g_nw[N_ATOMS*DIM];
__device__ float g_aggp[NSPLIT][N_ATOMS*DIM];  // per-i-split partial aggregates
__device__ float g_ha[N_ATOMS];
// paired-row fp16 tables: entry t = {row t, row t+1}, 128 halves (256B) per entry.
// lane g reads 16B at entry*256 + g*16 = {lo(4g..4g+3), hi(4g..4g+3)} via one LDG.128.
__device__ __align__(256) __half g_tab2[3][TABM*128];    // 96KB per layer
__device__ __align__(256) __half g_tabro2[TABRO*128];    // 128KB readout

__device__ __forceinline__ float sp05(float x){   // Softplus(beta=0.5, thr=14)
    float bx = 0.5f*x;
    return bx > 14.0f ? x : 2.0f*log1pf(expf(bx));
}
__device__ __forceinline__ float sp1(float x){    // Softplus(beta=1, thr=20)
    return x > 20.0f ? x : log1pf(expf(x));
}

// pair-layout half offset for row value of dim c: lo slot in pair[t], hi slot in pair[t-1]
__device__ __forceinline__ int pair_lo(int t, int c){ return t*128 + ((c>>2)<<3) + (c&3); }
__device__ __forceinline__ int pair_hi(int t, int c){ return t*128 + ((c>>2)<<3) + 4 + (c&3); }

// ---- fused preamble: paired tables + h/nw init ----
// blocks [0,384): layer tabs ; [384,896): ro ; [896,1664): init
__global__ void k_pre(const float* __restrict__ pw1, const float* __restrict__ pb1,
                      const float* __restrict__ pw2, const float* __restrict__ pb2,
                      const float* __restrict__ row1, const float* __restrict__ rob1,
                      const int* __restrict__ at, const float* __restrict__ emb,
                      const float* __restrict__ w1){
    int b = blockIdx.x, c = threadIdx.x;
    __shared__ float sbuf[DIM];
    __shared__ float rbf[NC];
    if (b < TABM){
        float d = (float)b * (CUTF/(float)(TABM-1));
        if (c < NC){ float t = d - (float)c*GAPF; rbf[c] = expf(-t*t*(1.0f/GAPF)); }
        __syncthreads();
        for (int l=0;l<3;l++){
            float u0 = pb1[l*DIM+c], u1 = 0.f;
            #pragma unroll 10
            for (int k=0;k<NC-1;k+=2){
                u0 = fmaf(rbf[k],   pw1[(l*NC+k)*DIM+c],   u0);
                u1 = fmaf(rbf[k+1], pw1[(l*NC+k+1)*DIM+c], u1);
            }
            u0 = fmaf(rbf[NC-1], pw1[(l*NC+NC-1)*DIM+c], u0);
            float s = sp05(u0 + u1);
            sbuf[c] = s; __syncthreads();
            float e0 = pb2[l*DIM+c], e1 = 0.f;
            #pragma unroll 8
            for (int k=0;k<DIM;k+=2){
                e0 = fmaf(sbuf[k],   pw2[(l*DIM+k)*DIM+c],   e0);
                e1 = fmaf(sbuf[k+1], pw2[(l*DIM+k+1)*DIM+c], e1);
            }
            __half hv = __float2half(e0 + e1);
            if (b <= TABM-2) g_tab2[l][pair_lo(b, c)]   = hv;   // row b = lo of pair b
            if (b >= 1)      g_tab2[l][pair_hi(b-1, c)] = hv;   // row b = hi of pair b-1
            __syncthreads();
        }
    } else if (b < TABM + TABRO){
        int m = b - TABM;
        float d = (float)m * (CUTF/(float)(TABRO-1));
        if (c < NC){ float t = d - (float)c*GAPF; rbf[c] = expf(-t*t*(1.0f/GAPF)); }
        __syncthreads();
        float v0 = rob1[c], v1 = 0.f;
        #pragma unroll 10
        for (int k=0;k<NC-1;k+=2){
            v0 = fmaf(rbf[k],   row1[(2+k)*DIM+c],   v0);
            v1 = fmaf(rbf[k+1], row1[(2+k+1)*DIM+c], v1);
        }
        v0 = fmaf(rbf[NC-1], row1[(2+NC-1)*DIM+c], v0);
        __half hv = __float2half(v0 + v1);
        if (m <= TABRO-2) g_tabro2[pair_lo(m, c)]   = hv;
        if (m >= 1)       g_tabro2[pair_hi(m-1, c)] = hv;
    } else {
        int n = b - TABM - TABRO;
        float hv = emb[at[n]*DIM + c];
        sbuf[c] = hv; g_h[n*DIM+c] = hv;
        __syncthreads();
        float a0 = 0.f, a1 = 0.f;
        #pragma unroll 8
        for (int k=0;k<DIM;k+=2){
            a0 = fmaf(sbuf[k],   w1[k*DIM+c],     a0);
            a1 = fmaf(sbuf[k+1], w1[(k+1)*DIM+c], a1);
        }
        g_nw[n*DIM+c] = a0 + a1;
    }
}

// ---- message pass: aggp[isp][j] = sum_{i in split, i != j} nw[i] * lerp(tab_l, d_ij)
// grid (48, 24). One L1-hit LDG.128 per lane-edge (96KB table); HFMA2 lerp;
// branchless with analytic i==j correction (f=0 lerp is exact in half).
__global__ void __launch_bounds__(256,6) k_msg(const float* __restrict__ dist, int l){
    __shared__ float4 nw_s[IPB*16];     // 8 KB
    __shared__ uint2  ed_s[IPB*JPB];    // 4 KB : {f packed half2, t*256}

    int tid  = threadIdx.x;
    int grp  = tid >> 4;         // j within tile
    int g    = tid & 15;         // float4 lane
    int jbase = blockIdx.x * JPB;
    int ibase = blockIdx.y * IPB;
    int j     = jbase + grp;

    // stage nw chunk (IPB*16 float4 = 512), coalesced register-batched
    {
        const float4* __restrict__ nwg = (const float4*)g_nw + ibase*16;
        float4 rn[2];
        #pragma unroll
        for (int q=0;q<2;q++) rn[q] = __ldg(nwg + tid + 256*q);
        #pragma unroll
        for (int q=0;q<2;q++) nw_s[tid + 256*q] = rn[q];
    }
    // stage per-edge (f half2, byte offset t*256): index math ONCE per edge
    {
        uint2 rd[2];
        #pragma unroll
        for (int q=0;q<2;q++){
            int s = tid + 256*q;
            int il = s >> 4, jj = s & 15;
            int i = ibase + il, jd = jbase + jj;
            float dv = (i != jd) ? __ldg(dist + i*NM1 + jd - (jd > i)) : 0.f;
            float x = dv * INVH;
            int t = min((int)x, TABM-2);
            __half2 f2 = __float2half2_rn(x - (float)t);
            rd[q] = make_uint2(*reinterpret_cast<unsigned*>(&f2), (unsigned)t * 256u);
        }
        #pragma unroll
        for (int q=0;q<2;q++) ed_s[tid + 256*q] = rd[q];
    }
    __syncthreads();

    const char* __restrict__ tp = (const char*)g_tab2[l] + g*16;
    float4 acc = make_float4(0.f,0.f,0.f,0.f);
    #pragma unroll 4
    for (int il = 0; il < IPB; il++){
        uint2 ed = ed_s[il*16 + grp];
        uint4 a = __ldg((const uint4*)(tp + ed.y));   // {lo01, lo23, hi01, hi23}
        __half2 f2  = *reinterpret_cast<__half2*>(&ed.x);
        __half2 lo0 = *reinterpret_cast<__half2*>(&a.x);
        __half2 lo1 = *reinterpret_cast<__half2*>(&a.y);
        __half2 hi0 = *reinterpret_cast<__half2*>(&a.z);
        __half2 hi1 = *reinterpret_cast<__half2*>(&a.w);
        __half2 r0 = __hfma2(f2, __hsub2(hi0, lo0), lo0);
        __half2 r1 = __hfma2(f2, __hsub2(hi1, lo1), lo1);
        float4 w = nw_s[il*16 + g];
        acc.x = fmaf(w.x, __low2float(r0),  acc.x);
        acc.y = fmaf(w.y, __high2float(r0), acc.y);
        acc.z = fmaf(w.z, __low2float(r1),  acc.z);
        acc.w = fmaf(w.w, __high2float(r1), acc.w);
    }
    // remove i==j self-term (computed with d=0 -> exact pair[0].lo)
    int jl = j - ibase;
    if (jl >= 0 && jl < IPB){
        uint4 a = *(const uint4*)tp;    // pair 0
        float2 u0 = __half22float2(*reinterpret_cast<const __half2*>(&a.x));
        float2 u1 = __half22float2(*reinterpret_cast<const __half2*>(&a.y));
        float4 w  = nw_s[jl*16 + g];
        acc.x -= w.x*u0.x; acc.y -= w.y*u0.y;
        acc.z -= w.z*u1.x; acc.w -= w.w*u1.y;
    }
    ((float4*)g_aggp[blockIdx.y])[j*16 + g] = acc;
}

// ---- node update: h += MLP(sum of agg partials); then nw for next layer, or ha ----
__global__ void __launch_bounds__(256) k_upd(int l, int last,
        const float* __restrict__ qw1, const float* __restrict__ qb1,
        const float* __restrict__ qw2, const float* __restrict__ qb2,
        const float* __restrict__ w1,
        const float* __restrict__ auw1, const float* __restrict__ aub1,
        const float* __restrict__ auw2, const float* __restrict__ aub2){
    extern __shared__ float sm[];
    float* wA  = sm;            // qw1[l]
    float* wB  = sm + 4096;     // qw2[l]
    float* wC  = sm + 8192;     // w1[l+1] or au_w1
    float* sa  = sm + 12288;
    float* st  = sm + 12544;
    float* sh  = sm + 12800;
    float* au2 = sm + 13056;

    int tid = threadIdx.x;
    int nd  = tid >> 6;
    int c   = tid & 63;
    int n   = blockIdx.x*4 + nd;

    {
        const float4* A4 = (const float4*)(qw1 + l*DIM*DIM);
        const float4* B4 = (const float4*)(qw2 + l*DIM*DIM);
        const float4* C4 = (const float4*)(last ? auw1 : (w1 + (l+1)*DIM*DIM));
        float4 ra[4], rb[4], rc[4];
        #pragma unroll
        for (int q=0;q<4;q++){
            ra[q] = __ldg(A4 + tid + 256*q);
            rb[q] = __ldg(B4 + tid + 256*q);
            rc[q] = __ldg(C4 + tid + 256*q);
        }
        #pragma unroll
        for (int q=0;q<4;q++){
            ((float4*)wA)[tid + 256*q] = ra[q];
            ((float4*)wB)[tid + 256*q] = rb[q];
            ((float4*)wC)[tid + 256*q] = rc[q];
        }
    }
    if (last && tid < DIM) au2[tid] = auw2[tid];

    int off = n*DIM + c;
    float a = 0.f;
    #pragma unroll
    for (int s = 0; s < NSPLIT; s++) a += g_aggp[s][off];
    sa[nd*DIM + c] = a;
    __syncthreads();

    float u0 = qb1[l*DIM+c], u1 = 0.f, u2 = 0.f, u3 = 0.f;
    #pragma unroll 4
    for (int k=0;k<DIM;k+=4){
        u0 = fmaf(sa[nd*DIM+k],   wA[k*DIM+c],     u0);
        u1 = fmaf(sa[nd*DIM+k+1], wA[(k+1)*DIM+c], u1);
        u2 = fmaf(sa[nd*DIM+k+2], wA[(k+2)*DIM+c], u2);
        u3 = fmaf(sa[nd*DIM+k+3], wA[(k+3)*DIM+c], u3);
    }
    st[nd*DIM + c] = sp05((u0+u1)+(u2+u3));
    __syncthreads();

    float p0 = qb2[l*DIM+c], p1 = 0.f, p2 = 0.f, p3 = 0.f;
    #pragma unroll 4
    for (int k=0;k<DIM;k+=4){
        p0 = fmaf(st[nd*DIM+k],   wB[k*DIM+c],     p0);
        p1 = fmaf(st[nd*DIM+k+1], wB[(k+1)*DIM+c], p1);
        p2 = fmaf(st[nd*DIM+k+2], wB[(k+2)*DIM+c], p2);
        p3 = fmaf(st[nd*DIM+k+3], wB[(k+3)*DIM+c], p3);
    }
    float hn = g_h[off] + ((p0+p1)+(p2+p3));
    g_h[off] = hn;
    sh[nd*DIM + c] = hn;
    __syncthreads();

    if (!last){
        float a0 = 0.f, a1 = 0.f, a2 = 0.f, a3 = 0.f;
        #pragma unroll 4
        for (int k=0;k<DIM;k+=4){
            a0 = fmaf(sh[nd*DIM+k],   wC[k*DIM+c],     a0);
            a1 = fmaf(sh[nd*DIM+k+1], wC[(k+1)*DIM+c], a1);
            a2 = fmaf(sh[nd*DIM+k+2], wC[(k+2)*DIM+c], a2);
            a3 = fmaf(sh[nd*DIM+k+3], wC[(k+3)*DIM+c], a3);
        }
        g_nw[off] = (a0+a1)+(a2+a3);
    } else {
        float a0 = aub1[c], a1 = 0.f, a2 = 0.f, a3 = 0.f;
        #pragma unroll 4
        for (int k=0;k<DIM;k+=4){
            a0 = fmaf(sh[nd*DIM+k],   wC[k*DIM+c],     a0);
            a1 = fmaf(sh[nd*DIM+k+1], wC[(k+1)*DIM+c], a1);
            a2 = fmaf(sh[nd*DIM+k+2], wC[(k+2)*DIM+c], a2);
            a3 = fmaf(sh[nd*DIM+k+3], wC[(k+3)*DIM+c], a3);
        }
        st[nd*DIM + c] = sp1((a0+a1)+(a2+a3)) - LN2F;
        __syncthreads();
        if (c == 0){
            float acc2 = aub2[0];
            #pragma unroll 8
            for (int k=0;k<DIM;k++) acc2 = fmaf(st[nd*DIM+k], au2[k], acc2);
            g_ha[n] = acc2;
        }
    }
}

// ---- readout: i-major; per-edge scalars staged in smem; paired fp16 table ----
__global__ void __launch_bounds__(256) k_readout(const float* __restrict__ dist,
        const float* __restrict__ row1, const float* __restrict__ row2,
        const float* __restrict__ rob2, float* __restrict__ out){
    __shared__ float4 ed_s[NM1 + 1];
    int i   = blockIdx.x;
    int tid = threadIdx.x;
    int grp = tid >> 4;
    int g   = tid & 15;
    long ebase = (long)i * NM1;

    // stage per-edge scalars: f, byte-offset into paired ro table, hj
    for (int r = tid; r < NM1; r += 256){
        int jd = r + (r >= i);
        float d = __ldg(dist + ebase + r);
        float x = d * INVHRO;
        int t = min((int)x, TABRO-2);
        float hj = __ldg(g_ha + jd);
        ed_s[r] = make_float4(x - (float)t, __uint_as_float((unsigned)t * 256u), hj, 0.f);
    }

    float4 wa  = __ldg((const float4*)row1 + g);          // ro_w1 row 0 (ha_src)
    float4 wb  = __ldg((const float4*)(row1 + DIM) + g);  // ro_w1 row 1 (ha_dst)
    float4 w2a = __ldg((const float4*)row2 + 2*g);
    float4 w2b = __ldg((const float4*)row2 + 2*g + 1);
    float b20 = rob2[0], b21 = rob2[1];
    float hi = __ldg(g_ha + i);
    float4 base = make_float4(hi*wa.x, hi*wa.y, hi*wa.z, hi*wa.w);
    const char* tp = (const char*)g_tabro2 + g*16;
    __syncthreads();

    for (int r = grp; r < NM1; r += 16){
        float4 ed = ed_s[r];
        uint4 a = __ldg((const uint4*)(tp + __float_as_uint(ed.y)));
        float2 u0 = __half22float2(*reinterpret_cast<const __half2*>(&a.x));
        float2 u1 = __half22float2(*reinterpret_cast<const __half2*>(&a.y));
        float2 v0 = __half22float2(*reinterpret_cast<const __half2*>(&a.z));
        float2 v1 = __half22float2(*reinterpret_cast<const __half2*>(&a.w));
        float f = ed.x, hj = ed.z;
        float z0 = fmaxf(fmaf(hj, wb.x, fmaf(f, v0.x-u0.x, u0.x) + base.x), 0.f);
        float z1 = fmaxf(fmaf(hj, wb.y, fmaf(f, v0.y-u0.y, u0.y) + base.y), 0.f);
        float z2 = fmaxf(fmaf(hj, wb.z, fmaf(f, v1.x-u1.x, u1.x) + base.z), 0.f);
        float z3 = fmaxf(fmaf(hj, wb.w, fmaf(f, v1.y-u1.y, u1.y) + base.w), 0.f);
        float a0 = z0*w2a.x + z1*w2a.z + z2*w2b.x + z3*w2b.z;
        float a1 = z0*w2a.y + z1*w2a.w + z2*w2b.y + z3*w2b.w;
        #pragma unroll
        for (int off=8; off; off>>=1){
            a0 += __shfl_xor_sync(0xffffffffu, a0, off);
            a1 += __shfl_xor_sync(0xffffffffu, a1, off);
        }
        if (g == 0){
            float l0 = a0 + b20, l1 = a1 + b21;
            float m = fmaxf(l0, l1);
            float e0 = __expf(l0 - m), e1 = __expf(l1 - m);
            float inv = 1.0f/(e0 + e1);
            ((float2*)out)[ebase + r] = make_float2(e0*inv, e1*inv);
        }
    }
}

extern "C" void kernel_launch(void* const* d_in, const int* in_sizes, int n_in,
                              void* d_out, int out_size){
    const int*   at   = (const int*)  d_in[0];
    const float* dist = (const float*)d_in[1];
    // d_in[2]=src, d_in[3]=dst (recomputed analytically; complete graph)
    const float* emb  = (const float*)d_in[4];
    const float* w1   = (const float*)d_in[5];
    const float* pw1  = (const float*)d_in[6];
    const float* pb1  = (const float*)d_in[7];
    const float* pw2  = (const float*)d_in[8];
    const float* pb2  = (const float*)d_in[9];
    const float* qw1  = (const float*)d_in[10];
    const float* qb1  = (const float*)d_in[11];
    const float* qw2  = (const float*)d_in[12];
    const float* qb2  = (const float*)d_in[13];
    const float* auw1 = (const float*)d_in[14];
    const float* aub1 = (const float*)d_in[15];
    const float* auw2 = (const float*)d_in[16];
    const float* aub2 = (const float*)d_in[17];
    const float* row1 = (const float*)d_in[18];
    const float* rob1 = (const float*)d_in[19];
    const float* row2 = (const float*)d_in[20];
    const float* rob2 = (const float*)d_in[21];
    float* out = (float*)d_out;

    cudaFuncSetAttribute(k_upd, cudaFuncAttributeMaxDynamicSharedMemorySize, SMEM_UPD);

    // launch index for ncu -s 5: 0:pre 1:msg 2:upd 3:msg 4:upd 5:msg <- profiled
    k_pre<<<TABM + TABRO + N_ATOMS, 64>>>(pw1, pb1, pw2, pb2, row1, rob1, at, emb, w1);
    for (int l = 0; l < 3; l++){
        k_msg<<<dim3(48, NSPLIT), 256>>>(dist, l);
        k_upd<<<192, 256, SMEM_UPD>>>(l, (l==2) ? 1 : 0, qw1, qb1, qw2, qb2, w1,
                                      auw1, aub1, auw2, aub2);
    }
    k_readout<<<N_ATOMS, 256>>>(dist, row1, row2, rob2, out);
}

// round 16
// speedup vs baseline: 1.1048x; 1.0358x over previous
#include <cuda_runtime.h>
#include <cuda_fp16.h>
#include <math.h>

#define N_ATOMS 768
#define NM1 767
#define NEDGE (768*767)
#define DIM 64
#define NC 50
#define TABM 384                 // paired fp16 layer table rows -> 96KB/layer (L1-resident)
#define TABRO 512
#define CUTF 5.0f
#define GAPF (5.0f/49.0f)
#define INVH ((float)(TABM-1)/CUTF)
#define INVHRO ((float)(TABRO-1)/CUTF)
#define LN2F 0.69314718055994531f

#define NSPLIT 16
#define IPB (N_ATOMS/NSPLIT)     // 48 i-rows per block
#define JPB 16                   // 16 dst per block

#define SMEM_UPD ((3*4096 + 3*256 + 64)*4)   // 52480 B

// ---- scratch (static device allocations; no runtime alloc) ----
__device__ float g_h[N_ATOMS*DIM];
__device__ float g_nw[N_ATOMS*DIM];
__device__ float g_aggp[NSPLIT][N_ATOMS*DIM];  // per-i-split partial aggregates
__device__ float g_ha[N_ATOMS];
// paired-row fp16 tables: entry t = {row t, row t+1}, 128 halves (256B) per entry.
// lane g reads 16B at entry*256 + g*16 = {lo(4g..4g+3), hi(4g..4g+3)} via one LDG.128.
__device__ __align__(256) __half g_tab2[3][TABM*128];    // 96KB per layer
__device__ __align__(256) __half g_tabro2[TABRO*128];    // 128KB readout

__device__ __forceinline__ float sp05(float x){   // Softplus(beta=0.5, thr=14)
    float bx = 0.5f*x;
    return bx > 14.0f ? x : 2.0f*log1pf(expf(bx));
}
__device__ __forceinline__ float sp1(float x){    // Softplus(beta=1, thr=20)
    return x > 20.0f ? x : log1pf(expf(x));
}

// pair-layout half offset for row value of dim c: lo slot in pair[t], hi slot in pair[t-1]
__device__ __forceinline__ int pair_lo(int t, int c){ return t*128 + ((c>>2)<<3) + (c&3); }
__device__ __forceinline__ int pair_hi(int t, int c){ return t*128 + ((c>>2)<<3) + 4 + (c&3); }

// ---- fused preamble: paired tables + h/nw init ----
// blocks [0,384): layer tabs ; [384,896): ro ; [896,1664): init
__global__ void k_pre(const float* __restrict__ pw1, const float* __restrict__ pb1,
                      const float* __restrict__ pw2, const float* __restrict__ pb2,
                      const float* __restrict__ row1, const float* __restrict__ rob1,
                      const int* __restrict__ at, const float* __restrict__ emb,
                      const float* __restrict__ w1){
    int b = blockIdx.x, c = threadIdx.x;
    __shared__ float sbuf[DIM];
    __shared__ float rbf[NC];
    if (b < TABM){
        float d = (float)b * (CUTF/(float)(TABM-1));
        if (c < NC){ float t = d - (float)c*GAPF; rbf[c] = expf(-t*t*(1.0f/GAPF)); }
        __syncthreads();
        for (int l=0;l<3;l++){
            float u0 = pb1[l*DIM+c], u1 = 0.f;
            #pragma unroll 10
            for (int k=0;k<NC-1;k+=2){
                u0 = fmaf(rbf[k],   pw1[(l*NC+k)*DIM+c],   u0);
                u1 = fmaf(rbf[k+1], pw1[(l*NC+k+1)*DIM+c], u1);
            }
            u0 = fmaf(rbf[NC-1], pw1[(l*NC+NC-1)*DIM+c], u0);
            float s = sp05(u0 + u1);
            sbuf[c] = s; __syncthreads();
            float e0 = pb2[l*DIM+c], e1 = 0.f;
            #pragma unroll 8
            for (int k=0;k<DIM;k+=2){
                e0 = fmaf(sbuf[k],   pw2[(l*DIM+k)*DIM+c],   e0);
                e1 = fmaf(sbuf[k+1], pw2[(l*DIM+k+1)*DIM+c], e1);
            }
            __half hv = __float2half(e0 + e1);
            if (b <= TABM-2) g_tab2[l][pair_lo(b, c)]   = hv;   // row b = lo of pair b
            if (b >= 1)      g_tab2[l][pair_hi(b-1, c)] = hv;   // row b = hi of pair b-1
            __syncthreads();
        }
    } else if (b < TABM + TABRO){
        int m = b - TABM;
        float d = (float)m * (CUTF/(float)(TABRO-1));
        if (c < NC){ float t = d - (float)c*GAPF; rbf[c] = expf(-t*t*(1.0f/GAPF)); }
        __syncthreads();
        float v0 = rob1[c], v1 = 0.f;
        #pragma unroll 10
        for (int k=0;k<NC-1;k+=2){
            v0 = fmaf(rbf[k],   row1[(2+k)*DIM+c],   v0);
            v1 = fmaf(rbf[k+1], row1[(2+k+1)*DIM+c], v1);
        }
        v0 = fmaf(rbf[NC-1], row1[(2+NC-1)*DIM+c], v0);
        __half hv = __float2half(v0 + v1);
        if (m <= TABRO-2) g_tabro2[pair_lo(m, c)]   = hv;
        if (m >= 1)       g_tabro2[pair_hi(m-1, c)] = hv;
    } else {
        int n = b - TABM - TABRO;
        float hv = emb[at[n]*DIM + c];
        sbuf[c] = hv; g_h[n*DIM+c] = hv;
        __syncthreads();
        float a0 = 0.f, a1 = 0.f;
        #pragma unroll 8
        for (int k=0;k<DIM;k+=2){
            a0 = fmaf(sbuf[k],   w1[k*DIM+c],     a0);
            a1 = fmaf(sbuf[k+1], w1[(k+1)*DIM+c], a1);
        }
        g_nw[n*DIM+c] = a0 + a1;
    }
}

// ---- message pass: aggp[isp][j] = sum_{i in split, i != j} nw[i] * lerp(tab_l, d_ij)
// grid (48, 16) = 768 blocks -> SINGLE WAVE at 6 CTAs/SM. One L1-hit LDG.128 per
// lane-edge; HFMA2 lerp, float accumulate; branchless with analytic i==j correction.
__global__ void __launch_bounds__(256,6) k_msg(const float* __restrict__ dist, int l){
    __shared__ float4 nw_s[IPB*16];     // 12 KB
    __shared__ uint2  ed_s[IPB*JPB];    // 6 KB : {f packed half2, t*256}

    int tid  = threadIdx.x;
    int grp  = tid >> 4;         // j within tile
    int g    = tid & 15;         // float4 lane
    int jbase = blockIdx.x * JPB;
    int ibase = blockIdx.y * IPB;
    int j     = jbase + grp;

    // stage nw chunk (IPB*16 = 768 float4), coalesced register-batched
    {
        const float4* __restrict__ nwg = (const float4*)g_nw + ibase*16;
        float4 rn[3];
        #pragma unroll
        for (int q=0;q<3;q++) rn[q] = __ldg(nwg + tid + 256*q);
        #pragma unroll
        for (int q=0;q<3;q++) nw_s[tid + 256*q] = rn[q];
    }
    // stage per-edge (f half2, byte offset t*256): index math ONCE per edge
    {
        uint2 rd[3];
        #pragma unroll
        for (int q=0;q<3;q++){
            int s = tid + 256*q;
            int il = s >> 4, jj = s & 15;
            int i = ibase + il, jd = jbase + jj;
            float dv = (i != jd) ? __ldg(dist + i*NM1 + jd - (jd > i)) : 0.f;
            float x = dv * INVH;
            int t = min((int)x, TABM-2);
            __half2 f2 = __float2half2_rn(x - (float)t);
            rd[q] = make_uint2(*reinterpret_cast<unsigned*>(&f2), (unsigned)t * 256u);
        }
        #pragma unroll
        for (int q=0;q<3;q++) ed_s[tid + 256*q] = rd[q];
    }
    __syncthreads();

    const char* __restrict__ tp = (const char*)g_tab2[l] + g*16;
    float4 acc = make_float4(0.f,0.f,0.f,0.f);
    #pragma unroll 4
    for (int il = 0; il < IPB; il++){
        uint2 ed = ed_s[il*16 + grp];
        uint4 a = __ldg((const uint4*)(tp + ed.y));   // {lo01, lo23, hi01, hi23}
        __half2 f2  = *reinterpret_cast<__half2*>(&ed.x);
        __half2 lo0 = *reinterpret_cast<__half2*>(&a.x);
        __half2 lo1 = *reinterpret_cast<__half2*>(&a.y);
        __half2 hi0 = *reinterpret_cast<__half2*>(&a.z);
        __half2 hi1 = *reinterpret_cast<__half2*>(&a.w);
        __half2 r0 = __hfma2(f2, __hsub2(hi0, lo0), lo0);
        __half2 r1 = __hfma2(f2, __hsub2(hi1, lo1), lo1);
        float4 w = nw_s[il*16 + g];
        acc.x = fmaf(w.x, __low2float(r0),  acc.x);
        acc.y = fmaf(w.y, __high2float(r0), acc.y);
        acc.z = fmaf(w.z, __low2float(r1),  acc.z);
        acc.w = fmaf(w.w, __high2float(r1), acc.w);
    }
    // remove i==j self-term (computed with d=0 -> exact pair[0].lo)
    int jl = j - ibase;
    if (jl >= 0 && jl < IPB){
        uint4 a = *(const uint4*)tp;    // pair 0
        float2 u0 = __half22float2(*reinterpret_cast<const __half2*>(&a.x));
        float2 u1 = __half22float2(*reinterpret_cast<const __half2*>(&a.y));
        float4 w  = nw_s[jl*16 + g];
        acc.x -= w.x*u0.x; acc.y -= w.y*u0.y;
        acc.z -= w.z*u1.x; acc.w -= w.w*u1.y;
    }
    ((float4*)g_aggp[blockIdx.y])[j*16 + g] = acc;
}

// ---- node update: h += MLP(sum of agg partials); then nw for next layer, or ha ----
__global__ void __launch_bounds__(256) k_upd(int l, int last,
        const float* __restrict__ qw1, const float* __restrict__ qb1,
        const float* __restrict__ qw2, const float* __restrict__ qb2,
        const float* __restrict__ w1,
        const float* __restrict__ auw1, const float* __restrict__ aub1,
        const float* __restrict__ auw2, const float* __restrict__ aub2){
    extern __shared__ float sm[];
    float* wA  = sm;            // qw1[l]
    float* wB  = sm + 4096;     // qw2[l]
    float* wC  = sm + 8192;     // w1[l+1] or au_w1
    float* sa  = sm + 12288;
    float* st  = sm + 12544;
    float* sh  = sm + 12800;
    float* au2 = sm + 13056;

    int tid = threadIdx.x;
    int nd  = tid >> 6;
    int c   = tid & 63;
    int n   = blockIdx.x*4 + nd;

    {
        const float4* A4 = (const float4*)(qw1 + l*DIM*DIM);
        const float4* B4 = (const float4*)(qw2 + l*DIM*DIM);
        const float4* C4 = (const float4*)(last ? auw1 : (w1 + (l+1)*DIM*DIM));
        float4 ra[4], rb[4], rc[4];
        #pragma unroll
        for (int q=0;q<4;q++){
            ra[q] = __ldg(A4 + tid + 256*q);
            rb[q] = __ldg(B4 + tid + 256*q);
            rc[q] = __ldg(C4 + tid + 256*q);
        }
        #pragma unroll
        for (int q=0;q<4;q++){
            ((float4*)wA)[tid + 256*q] = ra[q];
            ((float4*)wB)[tid + 256*q] = rb[q];
            ((float4*)wC)[tid + 256*q] = rc[q];
        }
    }
    if (last && tid < DIM) au2[tid] = auw2[tid];

    int off = n*DIM + c;
    float a = 0.f;
    #pragma unroll
    for (int s = 0; s < NSPLIT; s++) a += g_aggp[s][off];
    sa[nd*DIM + c] = a;
    __syncthreads();

    float u0 = qb1[l*DIM+c], u1 = 0.f, u2 = 0.f, u3 = 0.f;
    #pragma unroll 4
    for (int k=0;k<DIM;k+=4){
        u0 = fmaf(sa[nd*DIM+k],   wA[k*DIM+c],     u0);
        u1 = fmaf(sa[nd*DIM+k+1], wA[(k+1)*DIM+c], u1);
        u2 = fmaf(sa[nd*DIM+k+2], wA[(k+2)*DIM+c], u2);
        u3 = fmaf(sa[nd*DIM+k+3], wA[(k+3)*DIM+c], u3);
    }
    st[nd*DIM + c] = sp05((u0+u1)+(u2+u3));
    __syncthreads();

    float p0 = qb2[l*DIM+c], p1 = 0.f, p2 = 0.f, p3 = 0.f;
    #pragma unroll 4
    for (int k=0;k<DIM;k+=4){
        p0 = fmaf(st[nd*DIM+k],   wB[k*DIM+c],     p0);
        p1 = fmaf(st[nd*DIM+k+1], wB[(k+1)*DIM+c], p1);
        p2 = fmaf(st[nd*DIM+k+2], wB[(k+2)*DIM+c], p2);
        p3 = fmaf(st[nd*DIM+k+3], wB[(k+3)*DIM+c], p3);
    }
    float hn = g_h[off] + ((p0+p1)+(p2+p3));
    g_h[off] = hn;
    sh[nd*DIM + c] = hn;
    __syncthreads();

    if (!last){
        float a0 = 0.f, a1 = 0.f, a2 = 0.f, a3 = 0.f;
        #pragma unroll 4
        for (int k=0;k<DIM;k+=4){
            a0 = fmaf(sh[nd*DIM+k],   wC[k*DIM+c],     a0);
            a1 = fmaf(sh[nd*DIM+k+1], wC[(k+1)*DIM+c], a1);
            a2 = fmaf(sh[nd*DIM+k+2], wC[(k+2)*DIM+c], a2);
            a3 = fmaf(sh[nd*DIM+k+3], wC[(k+3)*DIM+c], a3);
        }
        g_nw[off] = (a0+a1)+(a2+a3);
    } else {
        float a0 = aub1[c], a1 = 0.f, a2 = 0.f, a3 = 0.f;
        #pragma unroll 4
        for (int k=0;k<DIM;k+=4){
            a0 = fmaf(sh[nd*DIM+k],   wC[k*DIM+c],     a0);
            a1 = fmaf(sh[nd*DIM+k+1], wC[(k+1)*DIM+c], a1);
            a2 = fmaf(sh[nd*DIM+k+2], wC[(k+2)*DIM+c], a2);
            a3 = fmaf(sh[nd*DIM+k+3], wC[(k+3)*DIM+c], a3);
        }
        st[nd*DIM + c] = sp1((a0+a1)+(a2+a3)) - LN2F;
        __syncthreads();
        if (c == 0){
            float acc2 = aub2[0];
            #pragma unroll 8
            for (int k=0;k<DIM;k++) acc2 = fmaf(st[nd*DIM+k], au2[k], acc2);
            g_ha[n] = acc2;
        }
    }
}

// ---- readout: i-major; per-edge scalars staged in smem; paired fp16 table ----
__global__ void __launch_bounds__(256) k_readout(const float* __restrict__ dist,
        const float* __restrict__ row1, const float* __restrict__ row2,
        const float* __restrict__ rob2, float* __restrict__ out){
    __shared__ float4 ed_s[NM1 + 1];
    int i   = blockIdx.x;
    int tid = threadIdx.x;
    int grp = tid >> 4;
    int g   = tid & 15;
    long ebase = (long)i * NM1;

    // stage per-edge scalars: f, byte-offset into paired ro table, hj
    for (int r = tid; r < NM1; r += 256){
        int jd = r + (r >= i);
        float d = __ldg(dist + ebase + r);
        float x = d * INVHRO;
        int t = min((int)x, TABRO-2);
        float hj = __ldg(g_ha + jd);
        ed_s[r] = make_float4(x - (float)t, __uint_as_float((unsigned)t * 256u), hj, 0.f);
    }

    float4 wa  = __ldg((const float4*)row1 + g);          // ro_w1 row 0 (ha_src)
    float4 wb  = __ldg((const float4*)(row1 + DIM) + g);  // ro_w1 row 1 (ha_dst)
    float4 w2a = __ldg((const float4*)row2 + 2*g);
    float4 w2b = __ldg((const float4*)row2 + 2*g + 1);
    float b20 = rob2[0], b21 = rob2[1];
    float hi = __ldg(g_ha + i);
    float4 base = make_float4(hi*wa.x, hi*wa.y, hi*wa.z, hi*wa.w);
    const char* tp = (const char*)g_tabro2 + g*16;
    __syncthreads();

    for (int r = grp; r < NM1; r += 16){
        float4 ed = ed_s[r];
        uint4 a = __ldg((const uint4*)(tp + __float_as_uint(ed.y)));
        float2 u0 = __half22float2(*reinterpret_cast<const __half2*>(&a.x));
        float2 u1 = __half22float2(*reinterpret_cast<const __half2*>(&a.y));
        float2 v0 = __half22float2(*reinterpret_cast<const __half2*>(&a.z));
        float2 v1 = __half22float2(*reinterpret_cast<const __half2*>(&a.w));
        float f = ed.x, hj = ed.z;
        float z0 = fmaxf(fmaf(hj, wb.x, fmaf(f, v0.x-u0.x, u0.x) + base.x), 0.f);
        float z1 = fmaxf(fmaf(hj, wb.y, fmaf(f, v0.y-u0.y, u0.y) + base.y), 0.f);
        float z2 = fmaxf(fmaf(hj, wb.z, fmaf(f, v1.x-u1.x, u1.x) + base.z), 0.f);
        float z3 = fmaxf(fmaf(hj, wb.w, fmaf(f, v1.y-u1.y, u1.y) + base.w), 0.f);
        float a0 = z0*w2a.x + z1*w2a.z + z2*w2b.x + z3*w2b.z;
        float a1 = z0*w2a.y + z1*w2a.w + z2*w2b.y + z3*w2b.w;
        #pragma unroll
        for (int off=8; off; off>>=1){
            a0 += __shfl_xor_sync(0xffffffffu, a0, off);
            a1 += __shfl_xor_sync(0xffffffffu, a1, off);
        }
        if (g == 0){
            float l0 = a0 + b20, l1 = a1 + b21;
            float m = fmaxf(l0, l1);
            float e0 = __expf(l0 - m), e1 = __expf(l1 - m);
            float inv = 1.0f/(e0 + e1);
            ((float2*)out)[ebase + r] = make_float2(e0*inv, e1*inv);
        }
    }
}

extern "C" void kernel_launch(void* const* d_in, const int* in_sizes, int n_in,
                              void* d_out, int out_size){
    const int*   at   = (const int*)  d_in[0];
    const float* dist = (const float*)d_in[1];
    // d_in[2]=src, d_in[3]=dst (recomputed analytically; complete graph)
    const float* emb  = (const float*)d_in[4];
    const float* w1   = (const float*)d_in[5];
    const float* pw1  = (const float*)d_in[6];
    const float* pb1  = (const float*)d_in[7];
    const float* pw2  = (const float*)d_in[8];
    const float* pb2  = (const float*)d_in[9];
    const float* qw1  = (const float*)d_in[10];
    const float* qb1  = (const float*)d_in[11];
    const float* qw2  = (const float*)d_in[12];
    const float* qb2  = (const float*)d_in[13];
    const float* auw1 = (const float*)d_in[14];
    const float* aub1 = (const float*)d_in[15];
    const float* auw2 = (const float*)d_in[16];
    const float* aub2 = (const float*)d_in[17];
    const float* row1 = (const float*)d_in[18];
    const float* rob1 = (const float*)d_in[19];
    const float* row2 = (const float*)d_in[20];
    const float* rob2 = (const float*)d_in[21];
    float* out = (float*)d_out;

    cudaFuncSetAttribute(k_upd, cudaFuncAttributeMaxDynamicSharedMemorySize, SMEM_UPD);

    // launch index for ncu -s 5: 0:pre 1:msg 2:upd 3:msg 4:upd 5:msg <- profiled
    k_pre<<<TABM + TABRO + N_ATOMS, 64>>>(pw1, pb1, pw2, pb2, row1, rob1, at, emb, w1);
    for (int l = 0; l < 3; l++){
        k_msg<<<dim3(48, NSPLIT), 256>>>(dist, l);
        k_upd<<<192, 256, SMEM_UPD>>>(l, (l==2) ? 1 : 0, qw1, qb1, qw2, qb2, w1,
                                      auw1, aub1, auw2, aub2);
    }
    k_readout<<<N_ATOMS, 256>>>(dist, row1, row2, rob2, out);
}